// round 1
// baseline (speedup 1.0000x reference)
#include <cuda_runtime.h>
#include <math.h>

#define NN 50000
#define EE 800000
#define ET (EE + NN)
#define GG 32

// ---------------- scratch (device globals; no allocation allowed) ----------
__device__ float g_xl[NN * 256];
__device__ float g_xr[NN * 256];
__device__ float g_b1[NN * 256];
__device__ float g_b2[NN * 256];
__device__ float g_s[(size_t)ET * 4];
__device__ int   g_deg[NN];
__device__ int   g_rowptr[NN + 1];
__device__ int   g_cursor[NN];
__device__ int   g_csrc[ET];
__device__ float g_mean[GG * 256];
__device__ float g_var[GG * 256];
__device__ float g_cnt[GG];
__device__ float g_feat[GG * 16];

// ---------------- helpers ---------------------------------------------------
__device__ __forceinline__ int enc_f(float f) {
    int i = __float_as_int(f);
    return i >= 0 ? i : i ^ 0x7fffffff;
}
__device__ __forceinline__ float dec_f(int i) {
    return __int_as_float(i >= 0 ? i : i ^ 0x7fffffff);
}

// ---------------- CSR build -------------------------------------------------
__global__ void k_init_deg() {
    int i = blockIdx.x * blockDim.x + threadIdx.x;
    if (i < NN) g_deg[i] = 1;  // self loop
}

__global__ void k_count(const int* __restrict__ ei) {
    int e = blockIdx.x * blockDim.x + threadIdx.x;
    if (e < EE) atomicAdd(&g_deg[ei[EE + e]], 1);
}

__global__ void k_scan() {
    __shared__ int sh[1024];
    __shared__ int carry;
    if (threadIdx.x == 0) carry = 0;
    __syncthreads();
    for (int base = 0; base < NN; base += 1024) {
        int i = base + threadIdx.x;
        int v = (i < NN) ? g_deg[i] : 0;
        sh[threadIdx.x] = v;
        __syncthreads();
        for (int off = 1; off < 1024; off <<= 1) {
            int t = (threadIdx.x >= off) ? sh[threadIdx.x - off] : 0;
            __syncthreads();
            sh[threadIdx.x] += t;
            __syncthreads();
        }
        int excl = sh[threadIdx.x] - v;
        if (i < NN) {
            g_rowptr[i] = carry + excl;
            g_cursor[i] = carry + excl;
        }
        __syncthreads();
        if (threadIdx.x == 1023) carry += sh[1023];
        __syncthreads();
    }
    if (threadIdx.x == 0) g_rowptr[NN] = carry;
}

__global__ void k_scatter(const int* __restrict__ ei) {
    int e = blockIdx.x * blockDim.x + threadIdx.x;
    if (e < ET) {
        int s, d;
        if (e < EE) { s = ei[e]; d = ei[EE + e]; }
        else        { s = d = e - EE; }
        int p = atomicAdd(&g_cursor[d], 1);
        g_csrc[p] = s;
    }
}

__global__ void k_count_batch(const int* __restrict__ batch) {
    int i = blockIdx.x * blockDim.x + threadIdx.x;
    if (i < NN) atomicAdd(&g_cnt[batch[i]], 1.0f);
}

// ---------------- GEMM C = A@B + bias ---------------------------------------
// A [M,K] row-major, B [K,Nn] row-major, tile 64x64, BK=16, 256 threads, 4x4/thread
__global__ void k_gemm_bias(const float* __restrict__ A, const float* __restrict__ B,
                            const float* __restrict__ bias, float* __restrict__ C,
                            int M, int K, int Nn) {
    __shared__ float As[16][64];
    __shared__ float Bs[16][64];
    const int tid = threadIdx.x;
    const int row0 = blockIdx.y * 64, col0 = blockIdx.x * 64;
    const int tr = tid >> 4, tc = tid & 15;
    const int ar = tid >> 2, ac = (tid & 3) * 4;
    const int br = tid >> 4, bc = (tid & 15) * 4;
    float acc[4][4] = {};
    for (int k0 = 0; k0 < K; k0 += 16) {
        float4 av = make_float4(0.f, 0.f, 0.f, 0.f);
        if (row0 + ar < M)
            av = *(const float4*)(A + (size_t)(row0 + ar) * K + k0 + ac);
        As[ac + 0][ar] = av.x;
        As[ac + 1][ar] = av.y;
        As[ac + 2][ar] = av.z;
        As[ac + 3][ar] = av.w;
        float4 bv = *(const float4*)(B + (size_t)(k0 + br) * Nn + col0 + bc);
        *(float4*)&Bs[br][bc] = bv;
        __syncthreads();
#pragma unroll
        for (int kk = 0; kk < 16; kk++) {
            float a[4], b[4];
#pragma unroll
            for (int i = 0; i < 4; i++) {
                a[i] = As[kk][tr * 4 + i];
                b[i] = Bs[kk][tc * 4 + i];
            }
#pragma unroll
            for (int i = 0; i < 4; i++)
#pragma unroll
                for (int j = 0; j < 4; j++) acc[i][j] = fmaf(a[i], b[j], acc[i][j]);
        }
        __syncthreads();
    }
#pragma unroll
    for (int i = 0; i < 4; i++) {
        int row = row0 + tr * 4 + i;
        if (row < M) {
#pragma unroll
            for (int j = 0; j < 4; j++) {
                int col = col0 + tc * 4 + j;
                C[(size_t)row * Nn + col] = acc[i][j] + bias[col];
            }
        }
    }
}

// ---------------- fused per-node GATv2 attention ----------------------------
// one block (256 threads) per dst node. CSR order. D in {64,32,16}, H=4.
template <int D, bool CONCAT>
__global__ void k_attn(const float* __restrict__ xl, const float* __restrict__ xr,
                       const float* __restrict__ att, const float* __restrict__ bias,
                       float* __restrict__ out) {
    constexpr int HD = 4 * D;
    const int node = blockIdx.x;
    const int tid = threadIdx.x, lane = tid & 31, wrp = tid >> 5;
    __shared__ float sh_xr[HD];
    __shared__ float sh_att[HD];
    __shared__ float sh_out[HD];
    __shared__ int   sh_max[4];
    __shared__ float sh_maxf[4];
    __shared__ float sh_den[4];
    __shared__ float sh_inv[4];

    if (tid < HD) {
        sh_xr[tid]  = xr[(size_t)node * HD + tid];
        sh_att[tid] = att[tid];
    }
    if (tid < 4) { sh_max[tid] = (int)0x80000000; sh_den[tid] = 0.f; }
    __syncthreads();

    const int beg = g_rowptr[node], end = g_rowptr[node + 1];

    // pass 1: scores + per-head max (warp per edge)
    for (int e = beg + wrp; e < end; e += 8) {
        const float* xs = xl + (size_t)g_csrc[e] * HD;
        float a0 = 0.f, a1 = 0.f, a2 = 0.f, a3 = 0.f;
#pragma unroll
        for (int c = lane; c < HD; c += 32) {
            float m = xs[c] + sh_xr[c];
            m = m > 0.f ? m : 0.2f * m;
            float v = m * sh_att[c];
            int h = c / D;
            if (h == 0) a0 += v;
            else if (h == 1) a1 += v;
            else if (h == 2) a2 += v;
            else a3 += v;
        }
#pragma unroll
        for (int o = 16; o; o >>= 1) {
            a0 += __shfl_xor_sync(0xffffffffu, a0, o);
            a1 += __shfl_xor_sync(0xffffffffu, a1, o);
            a2 += __shfl_xor_sync(0xffffffffu, a2, o);
            a3 += __shfl_xor_sync(0xffffffffu, a3, o);
        }
        if (lane == 0) {
            g_s[(size_t)e * 4 + 0] = a0;
            g_s[(size_t)e * 4 + 1] = a1;
            g_s[(size_t)e * 4 + 2] = a2;
            g_s[(size_t)e * 4 + 3] = a3;
            atomicMax(&sh_max[0], enc_f(a0));
            atomicMax(&sh_max[1], enc_f(a1));
            atomicMax(&sh_max[2], enc_f(a2));
            atomicMax(&sh_max[3], enc_f(a3));
        }
    }
    __syncthreads();
    if (tid < 4) sh_maxf[tid] = dec_f(sh_max[tid]);
    __syncthreads();

    // pass 1.5: exp + denom
    for (int e = beg + wrp; e < end; e += 8) {
        if (lane < 4) {
            float v = __expf(g_s[(size_t)e * 4 + lane] - sh_maxf[lane]);
            g_s[(size_t)e * 4 + lane] = v;
            atomicAdd(&sh_den[lane], v);
        }
    }
    __syncthreads();
    if (tid < 4) sh_inv[tid] = 1.f / (sh_den[tid] + 1e-16f);
    __syncthreads();

    // pass 2: weighted aggregation (thread per channel)
    float acc = 0.f;
    if (tid < HD) {
        const int h = tid / D;
        for (int e = beg; e < end; e++) {
            float alpha = g_s[(size_t)e * 4 + h] * sh_inv[h];
            acc = fmaf(alpha, xl[(size_t)g_csrc[e] * HD + tid], acc);
        }
    }
    if (CONCAT) {
        if (tid < HD) out[(size_t)node * HD + tid] = acc + bias[tid];
    } else {
        if (tid < HD) sh_out[tid] = acc;
        __syncthreads();
        if (tid < D) {
            float r = 0.25f * (sh_out[tid] + sh_out[D + tid] + sh_out[2 * D + tid] + sh_out[3 * D + tid]);
            out[(size_t)node * D + tid] = r + bias[tid];
        }
    }
}

// ---------------- GraphNorm -------------------------------------------------
__global__ void k_gn_sum(const float* __restrict__ x, const int* __restrict__ batch,
                         float* __restrict__ mean, int F) {
    int idx = blockIdx.x * blockDim.x + threadIdx.x;
    if (idx < NN * F) {
        int n = idx / F, f = idx - n * F;
        atomicAdd(&mean[batch[n] * F + f], x[idx]);
    }
}

__global__ void k_div_cnt(float* __restrict__ m, int F) {
    int i = blockIdx.x * blockDim.x + threadIdx.x;
    if (i < GG * F) m[i] /= fmaxf(g_cnt[i / F], 1.0f);
}

__global__ void k_gn_var(const float* __restrict__ x, const int* __restrict__ batch,
                         const float* __restrict__ mean, const float* __restrict__ a,
                         float* __restrict__ var, int F) {
    int idx = blockIdx.x * blockDim.x + threadIdx.x;
    if (idx < NN * F) {
        int n = idx / F, f = idx - n * F;
        float xc = x[idx] - a[f] * mean[batch[n] * F + f];
        atomicAdd(&var[batch[n] * F + f], xc * xc);
    }
}

__global__ void k_gn_apply(float* __restrict__ x, const int* __restrict__ batch,
                           const float* __restrict__ mean, const float* __restrict__ var,
                           const float* __restrict__ w, const float* __restrict__ bb,
                           const float* __restrict__ a, int F) {
    int idx = blockIdx.x * blockDim.x + threadIdx.x;
    if (idx < NN * F) {
        int n = idx / F, f = idx - n * F;
        int b = batch[n];
        float xc = x[idx] - a[f] * mean[b * F + f];
        float y = w[f] * xc * rsqrtf(var[b * F + f] + 1e-5f) + bb[f];
        x[idx] = y > 0.f ? y : 0.f;  // fused ReLU
    }
}

// ---------------- pooling + classifier head ---------------------------------
__global__ void k_pool(const float* __restrict__ h, const int* __restrict__ batch) {
    int idx = blockIdx.x * blockDim.x + threadIdx.x;
    if (idx < NN * 16) {
        int n = idx >> 4, f = idx & 15;
        atomicAdd(&g_feat[batch[n] * 16 + f], h[idx]);
    }
}

__global__ void k_head(const float* __restrict__ linW, const float* __restrict__ linB,
                       float* __restrict__ out) {
    __shared__ float sf[GG * 16];
    int tid = threadIdx.x;
    if (tid < GG * 16) {
        int g = tid / 16;
        float v = g_feat[tid] / fmaxf(g_cnt[g], 1.0f);
        sf[tid] = v;
        out[GG * 4 + tid] = v;  // features at offset 128
    }
    __syncthreads();
    if (tid < GG * 4) {
        int g = tid >> 2, c = tid & 3;
        float s = linB[c];
#pragma unroll
        for (int f = 0; f < 16; f++) s = fmaf(sf[g * 16 + f], linW[f * 4 + c], s);
        out[g * 4 + c] = s;  // logits at offset 0
    }
}

// ---------------- host orchestration ----------------------------------------
static void run_gemm(const float* A, const float* B, const float* bias, float* C,
                     int M, int K, int Nn) {
    dim3 grid((Nn + 63) / 64, (M + 63) / 64);
    k_gemm_bias<<<grid, 256>>>(A, B, bias, C, M, K, Nn);
}

static void run_graphnorm(float* x, const int* batch, const float* w, const float* bb,
                          const float* a, int F, float* mean, float* var) {
    cudaMemsetAsync(mean, 0, (size_t)GG * F * sizeof(float));
    cudaMemsetAsync(var, 0, (size_t)GG * F * sizeof(float));
    int total = NN * F;
    int blocks = (total + 255) / 256;
    k_gn_sum<<<blocks, 256>>>(x, batch, mean, F);
    k_div_cnt<<<(GG * F + 255) / 256, 256>>>(mean, F);
    k_gn_var<<<blocks, 256>>>(x, batch, mean, a, var, F);
    k_div_cnt<<<(GG * F + 255) / 256, 256>>>(var, F);
    k_gn_apply<<<blocks, 256>>>(x, batch, mean, var, w, bb, a, F);
}

extern "C" void kernel_launch(void* const* d_in, const int* in_sizes, int n_in,
                              void* d_out, int out_size) {
    const float* x     = (const float*)d_in[0];
    const int*   ei    = (const int*)d_in[1];
    const int*   batch = (const int*)d_in[2];
    const float* Wl1 = (const float*)d_in[3],  *bl1 = (const float*)d_in[4];
    const float* Wr1 = (const float*)d_in[5],  *br1 = (const float*)d_in[6];
    const float* att1 = (const float*)d_in[7], *bias1 = (const float*)d_in[8];
    const float* gw1 = (const float*)d_in[9],  *gb1 = (const float*)d_in[10], *ga1 = (const float*)d_in[11];
    const float* Wl2 = (const float*)d_in[12], *bl2 = (const float*)d_in[13];
    const float* Wr2 = (const float*)d_in[14], *br2 = (const float*)d_in[15];
    const float* att2 = (const float*)d_in[16], *bias2 = (const float*)d_in[17];
    const float* gw2 = (const float*)d_in[18], *gb2 = (const float*)d_in[19], *ga2 = (const float*)d_in[20];
    const float* Wl3 = (const float*)d_in[21], *bl3 = (const float*)d_in[22];
    const float* Wr3 = (const float*)d_in[23], *br3 = (const float*)d_in[24];
    const float* att3 = (const float*)d_in[25], *bias3 = (const float*)d_in[26];
    const float* gw3 = (const float*)d_in[27], *gb3 = (const float*)d_in[28], *ga3 = (const float*)d_in[29];
    const float* linW = (const float*)d_in[30], *linB = (const float*)d_in[31];

    float *xl, *xr, *b1, *b2, *mean, *var, *cnt, *feat;
    cudaGetSymbolAddress((void**)&xl, g_xl);
    cudaGetSymbolAddress((void**)&xr, g_xr);
    cudaGetSymbolAddress((void**)&b1, g_b1);
    cudaGetSymbolAddress((void**)&b2, g_b2);
    cudaGetSymbolAddress((void**)&mean, g_mean);
    cudaGetSymbolAddress((void**)&var, g_var);
    cudaGetSymbolAddress((void**)&cnt, g_cnt);
    cudaGetSymbolAddress((void**)&feat, g_feat);

    // ---- CSR build (per call; deterministic up to fp sum order) ----
    k_init_deg<<<(NN + 255) / 256, 256>>>();
    k_count<<<(EE + 255) / 256, 256>>>(ei);
    k_scan<<<1, 1024>>>();
    k_scatter<<<(ET + 255) / 256, 256>>>(ei);

    cudaMemsetAsync(cnt, 0, GG * sizeof(float));
    k_count_batch<<<(NN + 255) / 256, 256>>>(batch);

    // ---- layer 1: 128 -> 4x64 concat (256) ----
    run_gemm(x, Wl1, bl1, xl, NN, 128, 256);
    run_gemm(x, Wr1, br1, xr, NN, 128, 256);
    k_attn<64, true><<<NN, 256>>>(xl, xr, att1, bias1, b1);
    run_graphnorm(b1, batch, gw1, gb1, ga1, 256, mean, var);

    // ---- layer 2: 256 -> 4x32 concat (128) ----
    run_gemm(b1, Wl2, bl2, xl, NN, 256, 128);
    run_gemm(b1, Wr2, br2, xr, NN, 256, 128);
    k_attn<32, true><<<NN, 256>>>(xl, xr, att2, bias2, b2);
    run_graphnorm(b2, batch, gw2, gb2, ga2, 128, mean, var);

    // ---- layer 3: 128 -> 4x16 averaged (16) ----
    run_gemm(b2, Wl3, bl3, xl, NN, 128, 64);
    run_gemm(b2, Wr3, br3, xr, NN, 128, 64);
    k_attn<16, false><<<NN, 256>>>(xl, xr, att3, bias3, b1);
    run_graphnorm(b1, batch, gw3, gb3, ga3, 16, mean, var);

    // ---- global mean pool + linear head ----
    cudaMemsetAsync(feat, 0, GG * 16 * sizeof(float));
    k_pool<<<(NN * 16 + 255) / 256, 256>>>(b1, batch);
    k_head<<<1, 512>>>(linW, linB, (float*)d_out);
}

// round 2
// speedup vs baseline: 1.5142x; 1.5142x over previous
#include <cuda_runtime.h>
#include <math.h>

#define NN 50000
#define EE 800000
#define ET (EE + NN)
#define GG 32

// ---------------- scratch (device globals; no allocation allowed) ----------
__device__ float g_xl[NN * 256];
__device__ float g_xr[NN * 256];
__device__ float g_b1[NN * 256];
__device__ float g_b2[NN * 256];
__device__ int   g_deg[NN];
__device__ int   g_rowptr[NN + 1];
__device__ int   g_cursor[NN];
__device__ int   g_csrc[ET];
__device__ float g_sum[GG * 256];
__device__ float g_sq[GG * 256];
__device__ float g_cs[GG * 256];
__device__ float g_ct[GG * 256];
__device__ float g_cnt[GG];
__device__ float g_feat[GG * 16];

// ---------------- f32x2 packed helpers (Blackwell) --------------------------
__device__ __forceinline__ unsigned long long pack2(float lo, float hi) {
    unsigned long long r;
    asm("mov.b64 %0, {%1,%2};" : "=l"(r) : "f"(lo), "f"(hi));
    return r;
}
__device__ __forceinline__ void ffma2(unsigned long long& d, unsigned long long a,
                                      unsigned long long b) {
    asm("fma.rn.f32x2 %0, %1, %2, %0;" : "+l"(d) : "l"(a), "l"(b));
}

// ---------------- CSR build -------------------------------------------------
__global__ void k_init_deg() {
    int i = blockIdx.x * blockDim.x + threadIdx.x;
    if (i < NN) g_deg[i] = 1;  // self loop
}

__global__ void k_count(const int* __restrict__ ei) {
    int e = blockIdx.x * blockDim.x + threadIdx.x;
    if (e < EE) atomicAdd(&g_deg[ei[EE + e]], 1);
}

__global__ void k_scan() {
    __shared__ int sh[1024];
    __shared__ int carry;
    if (threadIdx.x == 0) carry = 0;
    __syncthreads();
    for (int base = 0; base < NN; base += 1024) {
        int i = base + threadIdx.x;
        int v = (i < NN) ? g_deg[i] : 0;
        sh[threadIdx.x] = v;
        __syncthreads();
        for (int off = 1; off < 1024; off <<= 1) {
            int t = (threadIdx.x >= off) ? sh[threadIdx.x - off] : 0;
            __syncthreads();
            sh[threadIdx.x] += t;
            __syncthreads();
        }
        int excl = sh[threadIdx.x] - v;
        if (i < NN) {
            g_rowptr[i] = carry + excl;
            g_cursor[i] = carry + excl;
        }
        __syncthreads();
        if (threadIdx.x == 1023) carry += sh[1023];
        __syncthreads();
    }
    if (threadIdx.x == 0) g_rowptr[NN] = carry;
}

__global__ void k_scatter(const int* __restrict__ ei) {
    int e = blockIdx.x * blockDim.x + threadIdx.x;
    if (e < ET) {
        int s, d;
        if (e < EE) { s = ei[e]; d = ei[EE + e]; }
        else        { s = d = e - EE; }
        int p = atomicAdd(&g_cursor[d], 1);
        g_csrc[p] = s;
    }
}

__global__ void k_count_batch(const int* __restrict__ batch) {
    int i = blockIdx.x * blockDim.x + threadIdx.x;
    if (i < NN) atomicAdd(&g_cnt[batch[i]], 1.0f);
}

// ---------------- GEMM C = A@B + bias (f32x2 packed) -------------------------
// A [M,K] row-major, B [K,Nn] row-major. Tile 128x64, BK=16, 256 threads,
// per-thread 8 rows x 4 cols, rows packed in pairs (f32x2).
__global__ void k_gemm_bias(const float* __restrict__ A, const float* __restrict__ B,
                            const float* __restrict__ bias, float* __restrict__ C,
                            int M, int K, int Nn) {
    __shared__ float As[16][128];   // [k][row]
    __shared__ float Bs[16][64];    // [k][col]
    const int tid = threadIdx.x;
    const int row0 = blockIdx.y * 128, col0 = blockIdx.x * 64;
    const int a_r = tid >> 2;            // 0..63 (two rows: a_r, a_r+64)
    const int a_c = (tid & 3) * 4;       // 0,4,8,12
    const int b_r = tid >> 4;            // 0..15
    const int b_c = (tid & 15) * 4;      // 0..60
    const int tr = tid >> 4;             // 0..15 -> rows tr*8..tr*8+7
    const int tc = tid & 15;             // cols tc*4..tc*4+3

    unsigned long long acc[4][4];        // [row-pair][col], each = 2 rows
#pragma unroll
    for (int i = 0; i < 4; i++)
#pragma unroll
        for (int j = 0; j < 4; j++) acc[i][j] = 0ull;

    for (int k0 = 0; k0 < K; k0 += 16) {
        // load A tile (transposed into smem)
        float4 av0 = make_float4(0.f, 0.f, 0.f, 0.f);
        float4 av1 = make_float4(0.f, 0.f, 0.f, 0.f);
        if (row0 + a_r < M)
            av0 = *(const float4*)(A + (size_t)(row0 + a_r) * K + k0 + a_c);
        if (row0 + a_r + 64 < M)
            av1 = *(const float4*)(A + (size_t)(row0 + a_r + 64) * K + k0 + a_c);
        As[a_c + 0][a_r] = av0.x;  As[a_c + 1][a_r] = av0.y;
        As[a_c + 2][a_r] = av0.z;  As[a_c + 3][a_r] = av0.w;
        As[a_c + 0][a_r + 64] = av1.x;  As[a_c + 1][a_r + 64] = av1.y;
        As[a_c + 2][a_r + 64] = av1.z;  As[a_c + 3][a_r + 64] = av1.w;
        // load B tile
        *(float4*)&Bs[b_r][b_c] = *(const float4*)(B + (size_t)(k0 + b_r) * Nn + col0 + b_c);
        __syncthreads();
#pragma unroll
        for (int kk = 0; kk < 16; kk++) {
            ulonglong2 a01 = *(const ulonglong2*)&As[kk][tr * 8];
            ulonglong2 a23 = *(const ulonglong2*)&As[kk][tr * 8 + 4];
            float4 b4 = *(const float4*)&Bs[kk][tc * 4];
            unsigned long long bd[4];
            bd[0] = pack2(b4.x, b4.x); bd[1] = pack2(b4.y, b4.y);
            bd[2] = pack2(b4.z, b4.z); bd[3] = pack2(b4.w, b4.w);
            unsigned long long ap[4] = {a01.x, a01.y, a23.x, a23.y};
#pragma unroll
            for (int i = 0; i < 4; i++)
#pragma unroll
                for (int j = 0; j < 4; j++) ffma2(acc[i][j], ap[i], bd[j]);
        }
        __syncthreads();
    }

    float4 bs = *(const float4*)&bias[col0 + tc * 4];
#pragma unroll
    for (int i2 = 0; i2 < 4; i2++) {
        int r0 = row0 + tr * 8 + i2 * 2;
        float2 v0 = *(float2*)&acc[i2][0];
        float2 v1 = *(float2*)&acc[i2][1];
        float2 v2 = *(float2*)&acc[i2][2];
        float2 v3 = *(float2*)&acc[i2][3];
        if (r0 < M) {
            float4 o = make_float4(v0.x + bs.x, v1.x + bs.y, v2.x + bs.z, v3.x + bs.w);
            *(float4*)(C + (size_t)r0 * Nn + col0 + tc * 4) = o;
        }
        if (r0 + 1 < M) {
            float4 o = make_float4(v0.y + bs.x, v1.y + bs.y, v2.y + bs.z, v3.y + bs.w);
            *(float4*)(C + (size_t)(r0 + 1) * Nn + col0 + tc * 4) = o;
        }
    }
}

// ---------------- fused single-pass GATv2 attention (online softmax) --------
// one block per dst node, blockDim = HD = 4*D. Each warp owns a strided subset
// of incoming edges, keeps running (max, denom, acc) per head; warps merged in smem.
template <int D, bool CONCAT>
__global__ void k_attn(const float* __restrict__ xl, const float* __restrict__ xr,
                       const float* __restrict__ att, const float* __restrict__ bias,
                       float* __restrict__ out) {
    constexpr int HD = 4 * D;
    constexpr int NW = HD / 32;  // warps per block == channel-regs per lane
    const int node = blockIdx.x;
    const int tid = threadIdx.x, lane = tid & 31, w = tid >> 5;
    __shared__ float sxr[HD], satt[HD];
    __shared__ float smx[NW][4], sden[NW][4];
    __shared__ float sacc[NW][HD];
    __shared__ float sfw[NW][4];
    __shared__ float sinv[4];

    sxr[tid] = xr[(size_t)node * HD + tid];
    satt[tid] = att[tid];
    __syncthreads();

    const int beg = g_rowptr[node], end = g_rowptr[node + 1];

    float mx[4] = {-1e30f, -1e30f, -1e30f, -1e30f};
    float den[4] = {0.f, 0.f, 0.f, 0.f};
    float acc[NW];
#pragma unroll
    for (int k = 0; k < NW; k++) acc[k] = 0.f;

    for (int e = beg + w; e < end; e += NW) {
        const float* xs = xl + (size_t)g_csrc[e] * HD;
        float xv[NW];
        float ph[4] = {0.f, 0.f, 0.f, 0.f};
#pragma unroll
        for (int k = 0; k < NW; k++) {
            int c = lane + 32 * k;
            float xval = xs[c];
            xv[k] = xval;
            float m = xval + sxr[c];
            m = m > 0.f ? m : 0.2f * m;
            int h = (D == 64) ? (k >> 1) : (D == 32) ? k : ((k << 1) + (lane >> 4));
            ph[h] = fmaf(m, satt[c], ph[h]);
        }
#pragma unroll
        for (int o = 16; o; o >>= 1) {
#pragma unroll
            for (int h = 0; h < 4; h++)
                ph[h] += __shfl_xor_sync(0xffffffffu, ph[h], o);
        }
        float f[4], wg[4];
#pragma unroll
        for (int h = 0; h < 4; h++) {
            float nm = fmaxf(mx[h], ph[h]);
            f[h] = __expf(mx[h] - nm);
            wg[h] = __expf(ph[h] - nm);
            den[h] = den[h] * f[h] + wg[h];
            mx[h] = nm;
        }
#pragma unroll
        for (int k = 0; k < NW; k++) {
            int h = (D == 64) ? (k >> 1) : (D == 32) ? k : ((k << 1) + (lane >> 4));
            acc[k] = fmaf(wg[h], xv[k], acc[k] * f[h]);
        }
    }
#pragma unroll
    for (int k = 0; k < NW; k++) sacc[w][lane + 32 * k] = acc[k];
    if (lane < 4) { smx[w][lane] = mx[lane]; sden[w][lane] = den[lane]; }
    __syncthreads();

    if (tid < 4) {
        float M = -1e30f;
#pragma unroll
        for (int i = 0; i < NW; i++) M = fmaxf(M, smx[i][tid]);
        float dt = 0.f;
#pragma unroll
        for (int i = 0; i < NW; i++) {
            float fw = __expf(smx[i][tid] - M);
            sfw[i][tid] = fw;
            dt += sden[i][tid] * fw;
        }
        sinv[tid] = 1.f / (dt + 1e-16f);
    }
    __syncthreads();

    {
        const int c = tid, h = c / D;
        float a = 0.f;
#pragma unroll
        for (int i = 0; i < NW; i++) a = fmaf(sacc[i][c], sfw[i][h], a);
        float r = a * sinv[h];
        if (CONCAT) {
            out[(size_t)node * HD + c] = r + bias[c];
        } else {
            sxr[c] = r;  // reuse smem for head-average
        }
    }
    if (!CONCAT) {
        __syncthreads();
        if (tid < D)
            out[(size_t)node * D + tid] =
                0.25f * (sxr[tid] + sxr[D + tid] + sxr[2 * D + tid] + sxr[3 * D + tid]) + bias[tid];
    }
}

// ---------------- GraphNorm (one-pass sum/sumsq + coef + apply) --------------
#define GN_CHUNK 64
__global__ void k_gn_reduce(const float* __restrict__ x, const int* __restrict__ batch,
                            int F) {
    __shared__ int sb[GN_CHUNK];
    const int tid = threadIdx.x;
    const int R = 256 / F < 1 ? 1 : 256 / F;  // node slices per block
    const int f = tid % F;
    const int r = tid / F;
    const int n0 = blockIdx.x * GN_CHUNK;
    if (tid < GN_CHUNK) sb[tid] = (n0 + tid < NN) ? batch[n0 + tid] : -1;
    __syncthreads();
    if (r >= R) return;
    float s = 0.f, q = 0.f;
    int cg = -1;
    for (int i = r; i < GN_CHUNK && n0 + i < NN; i += R) {
        int g = sb[i];
        if (g != cg) {
            if (cg >= 0) {
                atomicAdd(&g_sum[cg * F + f], s);
                atomicAdd(&g_sq[cg * F + f], q);
            }
            s = 0.f; q = 0.f; cg = g;
        }
        float v = x[(size_t)(n0 + i) * F + f];
        s += v;
        q = fmaf(v, v, q);
    }
    if (cg >= 0) {
        atomicAdd(&g_sum[cg * F + f], s);
        atomicAdd(&g_sq[cg * F + f], q);
    }
}

__global__ void k_gn_coef(const float* __restrict__ w, const float* __restrict__ b,
                          const float* __restrict__ a, int F) {
    int i = blockIdx.x * blockDim.x + threadIdx.x;
    if (i < GG * F) {
        int f = i % F;
        float c = fmaxf(g_cnt[i / F], 1.0f);
        float mean = g_sum[i] / c;
        float av = a[f];
        float var = g_sq[i] / c + mean * mean * (av * av - 2.f * av);
        var = fmaxf(var, 0.f);
        float s = w[f] * rsqrtf(var + 1e-5f);
        g_cs[i] = s;
        g_ct[i] = b[f] - s * av * mean;
    }
}

__global__ void k_gn_apply(float* __restrict__ x, const int* __restrict__ batch, int F) {
    int Fq = F >> 2;
    int idx = blockIdx.x * blockDim.x + threadIdx.x;
    if (idx < NN * Fq) {
        int n = idx / Fq, f4 = (idx - n * Fq) * 4;
        int g = batch[n];
        float4 xv = *(float4*)&x[(size_t)n * F + f4];
        float4 s = *(const float4*)&g_cs[g * F + f4];
        float4 t = *(const float4*)&g_ct[g * F + f4];
        float4 y;
        y.x = fmaxf(fmaf(s.x, xv.x, t.x), 0.f);
        y.y = fmaxf(fmaf(s.y, xv.y, t.y), 0.f);
        y.z = fmaxf(fmaf(s.z, xv.z, t.z), 0.f);
        y.w = fmaxf(fmaf(s.w, xv.w, t.w), 0.f);
        *(float4*)&x[(size_t)n * F + f4] = y;
    }
}

// ---------------- pooling + classifier head ---------------------------------
__global__ void k_pool(const float* __restrict__ h, const int* __restrict__ batch) {
    int idx = blockIdx.x * blockDim.x + threadIdx.x;
    if (idx < NN * 16) {
        int n = idx >> 4, f = idx & 15;
        atomicAdd(&g_feat[batch[n] * 16 + f], h[idx]);
    }
}

__global__ void k_head(const float* __restrict__ linW, const float* __restrict__ linB,
                       float* __restrict__ out) {
    __shared__ float sf[GG * 16];
    int tid = threadIdx.x;
    if (tid < GG * 16) {
        int g = tid / 16;
        float v = g_feat[tid] / fmaxf(g_cnt[g], 1.0f);
        sf[tid] = v;
        out[GG * 4 + tid] = v;  // features at offset 128
    }
    __syncthreads();
    if (tid < GG * 4) {
        int g = tid >> 2, c = tid & 3;
        float s = linB[c];
#pragma unroll
        for (int f = 0; f < 16; f++) s = fmaf(sf[g * 16 + f], linW[f * 4 + c], s);
        out[g * 4 + c] = s;  // logits at offset 0
    }
}

// ---------------- host orchestration ----------------------------------------
static void run_gemm(const float* A, const float* B, const float* bias, float* C,
                     int M, int K, int Nn) {
    dim3 grid((Nn + 63) / 64, (M + 127) / 128);
    k_gemm_bias<<<grid, 256>>>(A, B, bias, C, M, K, Nn);
}

static void run_graphnorm(float* x, const int* batch, const float* w, const float* bb,
                          const float* a, int F, float* sum, float* sq) {
    cudaMemsetAsync(sum, 0, (size_t)GG * F * sizeof(float));
    cudaMemsetAsync(sq, 0, (size_t)GG * F * sizeof(float));
    k_gn_reduce<<<(NN + GN_CHUNK - 1) / GN_CHUNK, 256>>>(x, batch, F);
    k_gn_coef<<<(GG * F + 255) / 256, 256>>>(w, bb, a, F);
    k_gn_apply<<<(NN * (F >> 2) + 255) / 256, 256>>>(x, batch, F);
}

extern "C" void kernel_launch(void* const* d_in, const int* in_sizes, int n_in,
                              void* d_out, int out_size) {
    const float* x     = (const float*)d_in[0];
    const int*   ei    = (const int*)d_in[1];
    const int*   batch = (const int*)d_in[2];
    const float* Wl1 = (const float*)d_in[3],  *bl1 = (const float*)d_in[4];
    const float* Wr1 = (const float*)d_in[5],  *br1 = (const float*)d_in[6];
    const float* att1 = (const float*)d_in[7], *bias1 = (const float*)d_in[8];
    const float* gw1 = (const float*)d_in[9],  *gb1 = (const float*)d_in[10], *ga1 = (const float*)d_in[11];
    const float* Wl2 = (const float*)d_in[12], *bl2 = (const float*)d_in[13];
    const float* Wr2 = (const float*)d_in[14], *br2 = (const float*)d_in[15];
    const float* att2 = (const float*)d_in[16], *bias2 = (const float*)d_in[17];
    const float* gw2 = (const float*)d_in[18], *gb2 = (const float*)d_in[19], *ga2 = (const float*)d_in[20];
    const float* Wl3 = (const float*)d_in[21], *bl3 = (const float*)d_in[22];
    const float* Wr3 = (const float*)d_in[23], *br3 = (const float*)d_in[24];
    const float* att3 = (const float*)d_in[25], *bias3 = (const float*)d_in[26];
    const float* gw3 = (const float*)d_in[27], *gb3 = (const float*)d_in[28], *ga3 = (const float*)d_in[29];
    const float* linW = (const float*)d_in[30], *linB = (const float*)d_in[31];

    float *xl, *xr, *b1, *b2, *sum, *sq, *cnt, *feat;
    cudaGetSymbolAddress((void**)&xl, g_xl);
    cudaGetSymbolAddress((void**)&xr, g_xr);
    cudaGetSymbolAddress((void**)&b1, g_b1);
    cudaGetSymbolAddress((void**)&b2, g_b2);
    cudaGetSymbolAddress((void**)&sum, g_sum);
    cudaGetSymbolAddress((void**)&sq, g_sq);
    cudaGetSymbolAddress((void**)&cnt, g_cnt);
    cudaGetSymbolAddress((void**)&feat, g_feat);

    // ---- CSR build ----
    k_init_deg<<<(NN + 255) / 256, 256>>>();
    k_count<<<(EE + 255) / 256, 256>>>(ei);
    k_scan<<<1, 1024>>>();
    k_scatter<<<(ET + 255) / 256, 256>>>(ei);

    cudaMemsetAsync(cnt, 0, GG * sizeof(float));
    k_count_batch<<<(NN + 255) / 256, 256>>>(batch);

    // ---- layer 1: 128 -> 4x64 concat (256) ----
    run_gemm(x, Wl1, bl1, xl, NN, 128, 256);
    run_gemm(x, Wr1, br1, xr, NN, 128, 256);
    k_attn<64, true><<<NN, 256>>>(xl, xr, att1, bias1, b1);
    run_graphnorm(b1, batch, gw1, gb1, ga1, 256, sum, sq);

    // ---- layer 2: 256 -> 4x32 concat (128) ----
    run_gemm(b1, Wl2, bl2, xl, NN, 256, 128);
    run_gemm(b1, Wr2, br2, xr, NN, 256, 128);
    k_attn<32, true><<<NN, 128>>>(xl, xr, att2, bias2, b2);
    run_graphnorm(b2, batch, gw2, gb2, ga2, 128, sum, sq);

    // ---- layer 3: 128 -> 4x16 averaged (16) ----
    run_gemm(b2, Wl3, bl3, xl, NN, 128, 64);
    run_gemm(b2, Wr3, br3, xr, NN, 128, 64);
    k_attn<16, false><<<NN, 64>>>(xl, xr, att3, bias3, b1);
    run_graphnorm(b1, batch, gw3, gb3, ga3, 16, sum, sq);

    // ---- global mean pool + linear head ----
    cudaMemsetAsync(feat, 0, GG * 16 * sizeof(float));
    k_pool<<<(NN * 16 + 255) / 256, 256>>>(b1, batch);
    k_head<<<1, 512>>>(linW, linB, (float*)d_out);
}